// round 1
// baseline (speedup 1.0000x reference)
#include <cuda_runtime.h>

#define E_DIM 128
#define NPG   32
#define NHEAD 8
#define HD    16
#define TPB   256
#define QPAD  132
#define KCHUNK 16

struct Smem {
    float X[NPG][E_DIM];    // input staging; later attention output
    float Q[NPG][QPAD];
    float K[NPG][QPAD];
    float V[NPG][QPAD];
    float Wt[KCHUNK][E_DIM]; // transposed weight K-chunk: Wt[kk][col] = W[col][e0+kk]
};

__device__ __forceinline__ void stage_rows(const float* __restrict__ src,
                                           float* __restrict__ dst, int tid) {
    const float4* s4 = reinterpret_cast<const float4*>(src);
    float4* d4 = reinterpret_cast<float4*>(dst);
#pragma unroll
    for (int i = 0; i < (NPG * E_DIM / 4) / TPB; i++)
        d4[i * TPB + tid] = s4[i * TPB + tid];
}

// out[r*ostride + c] = (sum_e X[r][e] * W[c][e] + bias[c]) * scale
// X is read from s.X (32 x 128). Internal __syncthreads() ordering guarantees:
// all reads of s.X and s.Wt complete before the trailing sync of the last
// K-chunk, so callers may overwrite s.X / s.Wt immediately after return.
__device__ __forceinline__ void gemm_32x128(
    Smem& s, const float* __restrict__ W, const float* __restrict__ bias,
    float scale, float* __restrict__ out, int ostride, int tid)
{
    const int ty = tid >> 4;   // 0..15 -> rows {ty, ty+16}
    const int tx = tid & 15;   // 0..15 -> cols [tx*8, tx*8+8)
    float acc[2][8];
#pragma unroll
    for (int i = 0; i < 2; i++)
#pragma unroll
        for (int j = 0; j < 8; j++) acc[i][j] = 0.f;

#pragma unroll
    for (int e0 = 0; e0 < E_DIM; e0 += KCHUNK) {
        // stage W[0..127][e0..e0+15] transposed into Wt[kk][col]
#pragma unroll
        for (int it = 0; it < 2; it++) {
            int idx  = it * TPB + tid;      // 0..511
            int col  = idx >> 2;            // 0..127
            int quad = (idx & 3) * 4;       // 0,4,8,12
            float4 w4 = *reinterpret_cast<const float4*>(W + col * E_DIM + e0 + quad);
            s.Wt[quad + 0][col] = w4.x;
            s.Wt[quad + 1][col] = w4.y;
            s.Wt[quad + 2][col] = w4.z;
            s.Wt[quad + 3][col] = w4.w;
        }
        __syncthreads();
#pragma unroll
        for (int kk = 0; kk < KCHUNK; kk++) {
            float a0 = s.X[ty][e0 + kk];
            float a1 = s.X[ty + 16][e0 + kk];
            float4 b0 = *reinterpret_cast<const float4*>(&s.Wt[kk][tx * 8]);
            float4 b1 = *reinterpret_cast<const float4*>(&s.Wt[kk][tx * 8 + 4]);
            acc[0][0] = fmaf(a0, b0.x, acc[0][0]);
            acc[0][1] = fmaf(a0, b0.y, acc[0][1]);
            acc[0][2] = fmaf(a0, b0.z, acc[0][2]);
            acc[0][3] = fmaf(a0, b0.w, acc[0][3]);
            acc[0][4] = fmaf(a0, b1.x, acc[0][4]);
            acc[0][5] = fmaf(a0, b1.y, acc[0][5]);
            acc[0][6] = fmaf(a0, b1.z, acc[0][6]);
            acc[0][7] = fmaf(a0, b1.w, acc[0][7]);
            acc[1][0] = fmaf(a1, b0.x, acc[1][0]);
            acc[1][1] = fmaf(a1, b0.y, acc[1][1]);
            acc[1][2] = fmaf(a1, b0.z, acc[1][2]);
            acc[1][3] = fmaf(a1, b0.w, acc[1][3]);
            acc[1][4] = fmaf(a1, b1.x, acc[1][4]);
            acc[1][5] = fmaf(a1, b1.y, acc[1][5]);
            acc[1][6] = fmaf(a1, b1.z, acc[1][6]);
            acc[1][7] = fmaf(a1, b1.w, acc[1][7]);
        }
        __syncthreads();
    }

    const float4 bA = *reinterpret_cast<const float4*>(bias + tx * 8);
    const float4 bB = *reinterpret_cast<const float4*>(bias + tx * 8 + 4);
    float4 r0, r1;
    r0.x = (acc[0][0] + bA.x) * scale; r0.y = (acc[0][1] + bA.y) * scale;
    r0.z = (acc[0][2] + bA.z) * scale; r0.w = (acc[0][3] + bA.w) * scale;
    r1.x = (acc[0][4] + bB.x) * scale; r1.y = (acc[0][5] + bB.y) * scale;
    r1.z = (acc[0][6] + bB.z) * scale; r1.w = (acc[0][7] + bB.w) * scale;
    *reinterpret_cast<float4*>(out + ty * ostride + tx * 8)     = r0;
    *reinterpret_cast<float4*>(out + ty * ostride + tx * 8 + 4) = r1;
    r0.x = (acc[1][0] + bA.x) * scale; r0.y = (acc[1][1] + bA.y) * scale;
    r0.z = (acc[1][2] + bA.z) * scale; r0.w = (acc[1][3] + bA.w) * scale;
    r1.x = (acc[1][4] + bB.x) * scale; r1.y = (acc[1][5] + bB.y) * scale;
    r1.z = (acc[1][6] + bB.z) * scale; r1.w = (acc[1][7] + bB.w) * scale;
    *reinterpret_cast<float4*>(out + (ty + 16) * ostride + tx * 8)     = r0;
    *reinterpret_cast<float4*>(out + (ty + 16) * ostride + tx * 8 + 4) = r1;
}

extern "C" __global__ void __launch_bounds__(TPB, 2)
iattn_fused_kernel(const float* __restrict__ query, const float* __restrict__ key,
                   const float* __restrict__ value,
                   const float* __restrict__ wq, const float* __restrict__ wk,
                   const float* __restrict__ wv,
                   const float* __restrict__ bq, const float* __restrict__ bk,
                   const float* __restrict__ bv,
                   const float* __restrict__ wo, const float* __restrict__ bo,
                   float* __restrict__ out)
{
    extern __shared__ char smem_raw[];
    Smem& s = *reinterpret_cast<Smem*>(smem_raw);
    const int g   = blockIdx.x;
    const int tid = threadIdx.x;
    const size_t base = (size_t)g * NPG * E_DIM;

    // --- QKV projections (q pre-scaled by 1/sqrt(D)=0.25, applied to bias too,
    //     matching reference: q = (x@W.T + b) / 4) ---
    stage_rows(query + base, &s.X[0][0], tid);
    gemm_32x128(s, wq, bq, 0.25f, &s.Q[0][0], QPAD, tid);
    stage_rows(key + base, &s.X[0][0], tid);
    gemm_32x128(s, wk, bk, 1.0f, &s.K[0][0], QPAD, tid);
    stage_rows(value + base, &s.X[0][0], tid);
    gemm_32x128(s, wv, bv, 1.0f, &s.V[0][0], QPAD, tid);
    __syncthreads();   // Q/K/V epilogue writes visible before attention reads

    // --- attention: warp = head, lane = query row; writes merged heads to s.X ---
    {
        const int h  = tid >> 5;
        const int l  = tid & 31;
        const int c0 = h * HD;
        const float4 q0 = *reinterpret_cast<const float4*>(&s.Q[l][c0]);
        const float4 q1 = *reinterpret_cast<const float4*>(&s.Q[l][c0 + 4]);
        const float4 q2 = *reinterpret_cast<const float4*>(&s.Q[l][c0 + 8]);
        const float4 q3 = *reinterpret_cast<const float4*>(&s.Q[l][c0 + 12]);

        float sc[NPG];
        float mx = -1e30f;
#pragma unroll
        for (int j = 0; j < NPG; j++) {
            const float4 k0 = *reinterpret_cast<const float4*>(&s.K[j][c0]);
            const float4 k1 = *reinterpret_cast<const float4*>(&s.K[j][c0 + 4]);
            const float4 k2 = *reinterpret_cast<const float4*>(&s.K[j][c0 + 8]);
            const float4 k3 = *reinterpret_cast<const float4*>(&s.K[j][c0 + 12]);
            float t;
            t = q0.x * k0.x;
            t = fmaf(q0.y, k0.y, t); t = fmaf(q0.z, k0.z, t); t = fmaf(q0.w, k0.w, t);
            t = fmaf(q1.x, k1.x, t); t = fmaf(q1.y, k1.y, t);
            t = fmaf(q1.z, k1.z, t); t = fmaf(q1.w, k1.w, t);
            t = fmaf(q2.x, k2.x, t); t = fmaf(q2.y, k2.y, t);
            t = fmaf(q2.z, k2.z, t); t = fmaf(q2.w, k2.w, t);
            t = fmaf(q3.x, k3.x, t); t = fmaf(q3.y, k3.y, t);
            t = fmaf(q3.z, k3.z, t); t = fmaf(q3.w, k3.w, t);
            sc[j] = t;
            mx = fmaxf(mx, t);
        }
        float sum = 0.f;
#pragma unroll
        for (int j = 0; j < NPG; j++) { sc[j] = __expf(sc[j] - mx); sum += sc[j]; }
        const float inv = 1.0f / sum;

        float o[HD];
#pragma unroll
        for (int d = 0; d < HD; d++) o[d] = 0.f;
#pragma unroll
        for (int j = 0; j < NPG; j++) {
            const float p = sc[j];
            const float4 v0 = *reinterpret_cast<const float4*>(&s.V[j][c0]);
            const float4 v1 = *reinterpret_cast<const float4*>(&s.V[j][c0 + 4]);
            const float4 v2 = *reinterpret_cast<const float4*>(&s.V[j][c0 + 8]);
            const float4 v3 = *reinterpret_cast<const float4*>(&s.V[j][c0 + 12]);
            o[0]  = fmaf(p, v0.x, o[0]);  o[1]  = fmaf(p, v0.y, o[1]);
            o[2]  = fmaf(p, v0.z, o[2]);  o[3]  = fmaf(p, v0.w, o[3]);
            o[4]  = fmaf(p, v1.x, o[4]);  o[5]  = fmaf(p, v1.y, o[5]);
            o[6]  = fmaf(p, v1.z, o[6]);  o[7]  = fmaf(p, v1.w, o[7]);
            o[8]  = fmaf(p, v2.x, o[8]);  o[9]  = fmaf(p, v2.y, o[9]);
            o[10] = fmaf(p, v2.z, o[10]); o[11] = fmaf(p, v2.w, o[11]);
            o[12] = fmaf(p, v3.x, o[12]); o[13] = fmaf(p, v3.y, o[13]);
            o[14] = fmaf(p, v3.z, o[14]); o[15] = fmaf(p, v3.w, o[15]);
        }
#pragma unroll
        for (int d = 0; d < HD; d += 4) {
            float4 r;
            r.x = o[d] * inv; r.y = o[d + 1] * inv;
            r.z = o[d + 2] * inv; r.w = o[d + 3] * inv;
            *reinterpret_cast<float4*>(&s.X[l][c0 + d]) = r;
        }
    }
    // gemm's first internal __syncthreads (after the Wt stage) orders the
    // attention writes to s.X before any thread reads s.X in the compute loop.
    gemm_32x128(s, wo, bo, 1.0f, out + base, E_DIM, tid);
}

extern "C" void kernel_launch(void* const* d_in, const int* in_sizes, int n_in,
                              void* d_out, int out_size)
{
    const float* query = (const float*)d_in[0];
    const float* key_  = (const float*)d_in[1];
    const float* value = (const float*)d_in[2];
    const float* wq    = (const float*)d_in[3];
    const float* wk    = (const float*)d_in[4];
    const float* wv    = (const float*)d_in[5];
    const float* bq    = (const float*)d_in[6];
    const float* bk    = (const float*)d_in[7];
    const float* bv    = (const float*)d_in[8];
    const float* wo    = (const float*)d_in[9];
    const float* bo    = (const float*)d_in[10];
    float* out = (float*)d_out;

    const int N = in_sizes[0] / E_DIM;   // total nodes
    const int G = N / NPG;               // graphs (CTAs)

    cudaFuncSetAttribute(iattn_fused_kernel,
                         cudaFuncAttributeMaxDynamicSharedMemorySize,
                         (int)sizeof(Smem));
    iattn_fused_kernel<<<G, TPB, sizeof(Smem)>>>(
        query, key_, value, wq, wk, wv, bq, bk, bv, wo, bo, out);
}

// round 2
// speedup vs baseline: 2.0674x; 2.0674x over previous
#include <cuda_runtime.h>

#define E_DIM 128
#define NPG   32
#define NHEAD 8
#define HD    16
#define NG    4             // graphs per CTA
#define ROWS  (NG * NPG)    // 128
#define TPB   256
#define PAD   132
#define KC    16            // k-chunk depth

typedef unsigned long long ull;

struct Smem {
    float QA[ROWS * PAD];   // Q (row-major [r][c]); later AttT (transposed [c][r])
    float Kh[ROWS * PAD];
    float Vh[ROWS * PAD];
    float Wt[KC * PAD];     // Wt[kk][col] = W[col][e0+kk]
    float Xt[KC * PAD];     // Xt[kk][row] = X[row][e0+kk]
};

__device__ __forceinline__ ull pack2(float lo, float hi) {
    ull r; asm("mov.b64 %0, {%1, %2};" : "=l"(r) : "f"(lo), "f"(hi)); return r;
}
__device__ __forceinline__ void unpack2(ull p, float& lo, float& hi) {
    asm("mov.b64 {%0, %1}, %2;" : "=f"(lo), "=f"(hi) : "l"(p));
}
__device__ __forceinline__ void ffma2(ull& d, ull a, ull b) {
    asm("fma.rn.f32x2 %0, %1, %2, %0;" : "+l"(d) : "l"(a), "l"(b));
}

// out[r][c] = (sum_k X[r][k] * W[c][k] + bias[c]) * scale   for a 128x128 tile, K=128.
// STAGE_X: X comes from gmem (row stride E_DIM), staged transposed per k-chunk.
// else:    X is already transposed in smem at aT ([k][row], stride PAD).
template<bool STAGE_X>
__device__ __forceinline__ void gemm128(
    Smem& s, const float* __restrict__ gx, const float* aT,
    const float* __restrict__ W, const float* __restrict__ bias,
    float scale, float* __restrict__ outp, int ostride, int tid)
{
    const int ty = tid >> 4;          // 0..15 -> rows [ty*8, ty*8+8)
    const int tx = tid & 15;          // 0..15 -> cols [tx*8, tx*8+8)
    const int r0s  = tid >> 2;        // staging row/col for first 256 elems
    const int r1s  = (TPB + tid) >> 2;
    const int quad = (tid & 3) * 4;

    ull acc[4][8];
#pragma unroll
    for (int i = 0; i < 4; i++)
#pragma unroll
        for (int j = 0; j < 8; j++) acc[i][j] = 0ULL;

    // prefetch chunk 0 into registers
    float4 wp0 = *reinterpret_cast<const float4*>(W + r0s * E_DIM + quad);
    float4 wp1 = *reinterpret_cast<const float4*>(W + r1s * E_DIM + quad);
    float4 xp0, xp1;
    if (STAGE_X) {
        xp0 = *reinterpret_cast<const float4*>(gx + r0s * E_DIM + quad);
        xp1 = *reinterpret_cast<const float4*>(gx + r1s * E_DIM + quad);
    }

#pragma unroll
    for (int c8 = 0; c8 < 8; c8++) {
        __syncthreads();   // previous chunk's compute (or prior phase) done
        s.Wt[(quad + 0) * PAD + r0s] = wp0.x;
        s.Wt[(quad + 1) * PAD + r0s] = wp0.y;
        s.Wt[(quad + 2) * PAD + r0s] = wp0.z;
        s.Wt[(quad + 3) * PAD + r0s] = wp0.w;
        s.Wt[(quad + 0) * PAD + r1s] = wp1.x;
        s.Wt[(quad + 1) * PAD + r1s] = wp1.y;
        s.Wt[(quad + 2) * PAD + r1s] = wp1.z;
        s.Wt[(quad + 3) * PAD + r1s] = wp1.w;
        if (STAGE_X) {
            s.Xt[(quad + 0) * PAD + r0s] = xp0.x;
            s.Xt[(quad + 1) * PAD + r0s] = xp0.y;
            s.Xt[(quad + 2) * PAD + r0s] = xp0.z;
            s.Xt[(quad + 3) * PAD + r0s] = xp0.w;
            s.Xt[(quad + 0) * PAD + r1s] = xp1.x;
            s.Xt[(quad + 1) * PAD + r1s] = xp1.y;
            s.Xt[(quad + 2) * PAD + r1s] = xp1.z;
            s.Xt[(quad + 3) * PAD + r1s] = xp1.w;
        }
        __syncthreads();
        if (c8 < 7) {       // prefetch next chunk (overlaps compute)
            const int e0n = (c8 + 1) * KC;
            wp0 = *reinterpret_cast<const float4*>(W + r0s * E_DIM + e0n + quad);
            wp1 = *reinterpret_cast<const float4*>(W + r1s * E_DIM + e0n + quad);
            if (STAGE_X) {
                xp0 = *reinterpret_cast<const float4*>(gx + r0s * E_DIM + e0n + quad);
                xp1 = *reinterpret_cast<const float4*>(gx + r1s * E_DIM + e0n + quad);
            }
        }
        const float* aB = STAGE_X ? s.Xt : (aT + c8 * KC * PAD);
#pragma unroll
        for (int kk = 0; kk < KC; kk++) {
            ulonglong2 a01 = *reinterpret_cast<const ulonglong2*>(aB + kk * PAD + ty * 8);
            ulonglong2 a23 = *reinterpret_cast<const ulonglong2*>(aB + kk * PAD + ty * 8 + 4);
            float4 b0 = *reinterpret_cast<const float4*>(s.Wt + kk * PAD + tx * 8);
            float4 b1 = *reinterpret_cast<const float4*>(s.Wt + kk * PAD + tx * 8 + 4);
            ull a2[4]; a2[0] = a01.x; a2[1] = a01.y; a2[2] = a23.x; a2[3] = a23.y;
            ull bd[8];
            bd[0] = pack2(b0.x, b0.x); bd[1] = pack2(b0.y, b0.y);
            bd[2] = pack2(b0.z, b0.z); bd[3] = pack2(b0.w, b0.w);
            bd[4] = pack2(b1.x, b1.x); bd[5] = pack2(b1.y, b1.y);
            bd[6] = pack2(b1.z, b1.z); bd[7] = pack2(b1.w, b1.w);
#pragma unroll
            for (int rp = 0; rp < 4; rp++)
#pragma unroll
                for (int c = 0; c < 8; c++)
                    ffma2(acc[rp][c], a2[rp], bd[c]);
        }
    }

    // epilogue: unpack, add bias, scale, store
    float b8[8];
    *reinterpret_cast<float4*>(b8)     = *reinterpret_cast<const float4*>(bias + tx * 8);
    *reinterpret_cast<float4*>(b8 + 4) = *reinterpret_cast<const float4*>(bias + tx * 8 + 4);
#pragma unroll
    for (int rp = 0; rp < 4; rp++) {
        float lo[8], hi[8];
#pragma unroll
        for (int c = 0; c < 8; c++) unpack2(acc[rp][c], lo[c], hi[c]);
        const int r0 = ty * 8 + rp * 2;
        float4 v;
        v.x = (lo[0] + b8[0]) * scale; v.y = (lo[1] + b8[1]) * scale;
        v.z = (lo[2] + b8[2]) * scale; v.w = (lo[3] + b8[3]) * scale;
        *reinterpret_cast<float4*>(outp + r0 * ostride + tx * 8) = v;
        v.x = (lo[4] + b8[4]) * scale; v.y = (lo[5] + b8[5]) * scale;
        v.z = (lo[6] + b8[6]) * scale; v.w = (lo[7] + b8[7]) * scale;
        *reinterpret_cast<float4*>(outp + r0 * ostride + tx * 8 + 4) = v;
        v.x = (hi[0] + b8[0]) * scale; v.y = (hi[1] + b8[1]) * scale;
        v.z = (hi[2] + b8[2]) * scale; v.w = (hi[3] + b8[3]) * scale;
        *reinterpret_cast<float4*>(outp + (r0 + 1) * ostride + tx * 8) = v;
        v.x = (hi[4] + b8[4]) * scale; v.y = (hi[5] + b8[5]) * scale;
        v.z = (hi[6] + b8[6]) * scale; v.w = (hi[7] + b8[7]) * scale;
        *reinterpret_cast<float4*>(outp + (r0 + 1) * ostride + tx * 8 + 4) = v;
    }
}

extern "C" __global__ void __launch_bounds__(TPB, 1)
iattn_fused2_kernel(const float* __restrict__ query, const float* __restrict__ key,
                    const float* __restrict__ value,
                    const float* __restrict__ wq, const float* __restrict__ wk,
                    const float* __restrict__ wv,
                    const float* __restrict__ bq, const float* __restrict__ bk,
                    const float* __restrict__ bv,
                    const float* __restrict__ wo, const float* __restrict__ bo,
                    float* __restrict__ out)
{
    extern __shared__ char raw[];
    Smem& s = *reinterpret_cast<Smem*>(raw);
    const int tid = threadIdx.x;
    const size_t base = (size_t)blockIdx.x * ROWS * E_DIM;

    // QKV projections (q scale 1/sqrt(16)=0.25 applied to acc+bias, matching ref)
    gemm128<true>(s, query + base, nullptr, wq, bq, 0.25f, s.QA, PAD, tid);
    gemm128<true>(s, key   + base, nullptr, wk, bk, 1.0f,  s.Kh, PAD, tid);
    gemm128<true>(s, value + base, nullptr, wv, bv, 1.0f,  s.Vh, PAD, tid);
    __syncthreads();   // QKV epilogue writes visible to attention

    // attention: warp = head h, lane = query row l; each warp covers NG graphs
    {
        const int h  = tid >> 5;
        const int l  = tid & 31;
        const int c0 = h * HD;
        float oall[NG][HD];
#pragma unroll
        for (int g = 0; g < NG; g++) {
            const float* qr = s.QA + (g * NPG + l) * PAD + c0;
            ulonglong2 qa = *reinterpret_cast<const ulonglong2*>(qr);
            ulonglong2 qb = *reinterpret_cast<const ulonglong2*>(qr + 4);
            ulonglong2 qc = *reinterpret_cast<const ulonglong2*>(qr + 8);
            ulonglong2 qd = *reinterpret_cast<const ulonglong2*>(qr + 12);

            float sc[NPG];
            float mx = -1e30f;
#pragma unroll
            for (int j = 0; j < NPG; j++) {
                const float* kr = s.Kh + (g * NPG + j) * PAD + c0;
                ulonglong2 ka = *reinterpret_cast<const ulonglong2*>(kr);
                ulonglong2 kb = *reinterpret_cast<const ulonglong2*>(kr + 4);
                ulonglong2 kc = *reinterpret_cast<const ulonglong2*>(kr + 8);
                ulonglong2 kd = *reinterpret_cast<const ulonglong2*>(kr + 12);
                ull t2 = 0ULL;
                ffma2(t2, qa.x, ka.x); ffma2(t2, qa.y, ka.y);
                ffma2(t2, qb.x, kb.x); ffma2(t2, qb.y, kb.y);
                ffma2(t2, qc.x, kc.x); ffma2(t2, qc.y, kc.y);
                ffma2(t2, qd.x, kd.x); ffma2(t2, qd.y, kd.y);
                float tl, th; unpack2(t2, tl, th);
                const float t = tl + th;
                sc[j] = t;
                mx = fmaxf(mx, t);
            }
            float sum = 0.f;
#pragma unroll
            for (int j = 0; j < NPG; j++) { sc[j] = __expf(sc[j] - mx); sum += sc[j]; }
            const float inv = 1.0f / sum;

            ull o2[8];
#pragma unroll
            for (int i = 0; i < 8; i++) o2[i] = 0ULL;
#pragma unroll
            for (int j = 0; j < NPG; j++) {
                const ull p2 = pack2(sc[j], sc[j]);
                const float* vr = s.Vh + (g * NPG + j) * PAD + c0;
                ulonglong2 va = *reinterpret_cast<const ulonglong2*>(vr);
                ulonglong2 vb = *reinterpret_cast<const ulonglong2*>(vr + 4);
                ulonglong2 vc = *reinterpret_cast<const ulonglong2*>(vr + 8);
                ulonglong2 vd = *reinterpret_cast<const ulonglong2*>(vr + 12);
                ffma2(o2[0], p2, va.x); ffma2(o2[1], p2, va.y);
                ffma2(o2[2], p2, vb.x); ffma2(o2[3], p2, vb.y);
                ffma2(o2[4], p2, vc.x); ffma2(o2[5], p2, vc.y);
                ffma2(o2[6], p2, vd.x); ffma2(o2[7], p2, vd.y);
            }
#pragma unroll
            for (int i = 0; i < 8; i++) {
                float lo, hi; unpack2(o2[i], lo, hi);
                oall[g][2 * i]     = lo * inv;
                oall[g][2 * i + 1] = hi * inv;
            }
        }
        __syncthreads();   // all Q/K/V reads done before overlaying AttT on QA
#pragma unroll
        for (int g = 0; g < NG; g++)
#pragma unroll
            for (int d = 0; d < HD; d++)
                s.QA[(c0 + d) * PAD + g * NPG + l] = oall[g][d];
    }
    __syncthreads();   // AttT visible

    // out-projection from transposed smem AttT
    gemm128<false>(s, nullptr, s.QA, wo, bo, 1.0f, out + base, E_DIM, tid);
}

extern "C" void kernel_launch(void* const* d_in, const int* in_sizes, int n_in,
                              void* d_out, int out_size)
{
    const float* query = (const float*)d_in[0];
    const float* key_  = (const float*)d_in[1];
    const float* value = (const float*)d_in[2];
    const float* wq    = (const float*)d_in[3];
    const float* wk    = (const float*)d_in[4];
    const float* wv    = (const float*)d_in[5];
    const float* bq    = (const float*)d_in[6];
    const float* bk    = (const float*)d_in[7];
    const float* bv    = (const float*)d_in[8];
    const float* wo    = (const float*)d_in[9];
    const float* bo    = (const float*)d_in[10];
    float* out = (float*)d_out;

    const int N = in_sizes[0] / E_DIM;   // total nodes
    const int G = N / NPG;               // graphs
    const int grid = G / NG;

    cudaFuncSetAttribute(iattn_fused2_kernel,
                         cudaFuncAttributeMaxDynamicSharedMemorySize,
                         (int)sizeof(Smem));
    iattn_fused2_kernel<<<grid, TPB, sizeof(Smem)>>>(
        query, key_, value, wq, wk, wv, bq, bk, bv, wo, bo, out);
}